// round 6
// baseline (speedup 1.0000x reference)
#include <cuda_runtime.h>
#include <cstdint>

// PlaceCellNetwork: 50 fixed-point iterations of
//   z_j = C_j + sum_i max(z_i,0) * G[i][j],  Y_j = inv_j * max(z_j, 0)
// Early exit never fires: exactly 50 iterations; rows independent.
// R6: VERTICAL (row-pair) packing. Each thread carries two rows A,B with
// z2[j] = {zA_j, zB_j}. Multiplier G pre-duplicated {g,g} in smem (800B broadcast
// LDS). relu(z2[i]) is used DIRECTLY as the packed FMA multiplier -> 20 FMNMX/iter
// (vs 40 for j-packing), 100 FFMA2/iter. Accumulation order (i ascending per j)
// identical to prior rounds -> same numerics.

#define DT    0.05f
#define LBD1  0.005f
#define LBD2  0.005f
#define NITER 50

typedef unsigned long long u64;

__device__ __align__(16) float g_Gd[200];  // [i*10+j] -> {g,g} duplicated pairs
__device__ __align__(16) float g_Wd[100];  // [k*10+j] -> {dt*W[j][k], dt*W[j][k]}
__device__ __align__(16) float g_C0d[20];  // [j] -> {-dt*b_j-lbd1} duplicated
__device__ __align__(16) float g_inv[12];  // 1/(lbd2 + M[j][j])

__global__ void setup_kernel(const float* __restrict__ W,
                             const float* __restrict__ M,
                             const float* __restrict__ b) {
    int t = threadIdx.x;
    if (t < 100) {
        int i = t / 10, j = t % 10;
        float H = (i == j) ? (1.0f - DT) : (-DT * M[i * 10 + j]);
        float g = H / (LBD2 + M[i * 10 + i]);
        g_Gd[2 * t] = g; g_Gd[2 * t + 1] = g;
    }
    if (t < 50) {
        int k = t / 10, j = t % 10;
        float w = DT * W[j * 5 + k];
        g_Wd[2 * t] = w; g_Wd[2 * t + 1] = w;
    }
    if (t < 10) {
        float c0 = -DT * b[t] - LBD1;
        g_C0d[2 * t] = c0; g_C0d[2 * t + 1] = c0;
        g_inv[t] = 1.0f / (LBD2 + M[t * 10 + t]);
    }
}

__device__ __forceinline__ u64 f2fma(u64 a, u64 b, u64 c) {
    u64 d;
    asm("fma.rn.f32x2 %0, %1, %2, %3;" : "=l"(d) : "l"(a), "l"(b), "l"(c));
    return d;
}
__device__ __forceinline__ u64 f2pack(float lo, float hi) {
    u64 d;
    asm("mov.b64 %0, {%1, %2};" : "=l"(d) : "f"(lo), "f"(hi));
    return d;
}
__device__ __forceinline__ void f2unpack(u64 v, float& lo, float& hi) {
    asm("mov.b64 {%0, %1}, %2;" : "=f"(lo), "=f"(hi) : "l"(v));
}
// Elementwise relu on a packed pair (2 FMNMX; pack/unpack are pair-allocation no-ops)
__device__ __forceinline__ u64 relu2(u64 v) {
    float lo, hi;
    f2unpack(v, lo, hi);
    return f2pack(fmaxf(lo, 0.0f), fmaxf(hi, 0.0f));
}

__global__ __launch_bounds__(128, 4)
void pcn_kernel(const float* __restrict__ X, float* __restrict__ Yout,
                int half, int rows) {
    // Duplicated coupling matrix in shared memory (broadcast, conflict-free)
    __shared__ __align__(16) u64 sG[100];
    int t = threadIdx.x;
    if (t < 50) ((ulonglong2*)sG)[t] = ((const ulonglong2*)g_Gd)[t];
    __syncthreads();

    int r = blockIdx.x * blockDim.x + t;
    if (r >= half) return;
    int r2 = r + half;
    if (r2 >= rows) r2 = r;   // odd-count guard; benign duplicate

    // Packed row inputs: Xp[k] = {xA_k, xB_k}
    u64 Xp[5];
#pragma unroll
    for (int k = 0; k < 5; k++)
        Xp[k] = f2pack(X[(size_t)r * 5 + k], X[(size_t)r2 * 5 + k]);

    // C2[j] = {CA_j, CB_j} = C0 + sum_k Xp[k] * Wdup[k][j]  (k=0 folds init)
    const u64* C0d = (const u64*)g_C0d;
    const u64* Wd  = (const u64*)g_Wd;
    u64 C2[10];
#pragma unroll
    for (int j = 0; j < 10; j++) C2[j] = f2fma(Xp[0], Wd[j], C0d[j]);
#pragma unroll
    for (int k = 1; k < 5; k++)
#pragma unroll
        for (int j = 0; j < 10; j++)
            C2[j] = f2fma(Xp[k], Wd[k * 10 + j], C2[j]);

    // z^(1) = C
    u64 z2[10];
#pragma unroll
    for (int j = 0; j < 10; j++) z2[j] = C2[j];

    // 49 more updates: V2 = relu2(z2) (used directly as multiplier, no dup);
    // z2[j] = C2[j] + sum_i V2[i]*Gdup[i][j], C folded into i=0.
#pragma unroll 1
    for (int it = 0; it < NITER - 1; it++) {
        u64 V2[10];
#pragma unroll
        for (int i = 0; i < 10; i++) V2[i] = relu2(z2[i]);
#pragma unroll
        for (int j = 0; j < 10; j++) z2[j] = f2fma(V2[0], sG[j], C2[j]);
#pragma unroll
        for (int i = 1; i < 10; i++)
#pragma unroll
            for (int j = 0; j < 10; j++)
                z2[j] = f2fma(V2[i], sG[i * 10 + j], z2[j]);
    }

    // Final activation + per-output scale; unpack to per-row float2 stores
    float2* out = (float2*)Yout;
    float A[10], Bv[10];
#pragma unroll
    for (int j = 0; j < 10; j++) {
        float lo, hi;
        f2unpack(z2[j], lo, hi);
        A[j]  = fmaxf(lo, 0.0f) * g_inv[j];
        Bv[j] = fmaxf(hi, 0.0f) * g_inv[j];
    }
#pragma unroll
    for (int p = 0; p < 5; p++) {
        float2 ya; ya.x = A[2 * p];  ya.y = A[2 * p + 1];
        out[(size_t)r * 5 + p] = ya;
        float2 yb; yb.x = Bv[2 * p]; yb.y = Bv[2 * p + 1];
        out[(size_t)r2 * 5 + p] = yb;
    }
}

extern "C" void kernel_launch(void* const* d_in, const int* in_sizes, int n_in,
                              void* d_out, int out_size) {
    // Identify inputs by element count: X=B*5, W=50, M=100, b=10
    const float *X = nullptr, *W = nullptr, *M = nullptr, *b = nullptr;
    int rows = 0;
    for (int i = 0; i < n_in; i++) {
        int s = in_sizes[i];
        const float* p = (const float*)d_in[i];
        if (s == 100) M = p;
        else if (s == 50) W = p;
        else if (s == 10) b = p;
        else { X = p; rows = s / 5; }
    }

    setup_kernel<<<1, 128>>>(W, M, b);

    int half = (rows + 1) / 2;
    const int threads = 128;
    int blocks = (half + threads - 1) / threads;
    pcn_kernel<<<blocks, threads>>>(X, (float*)d_out, half, rows);
}

// round 13
// speedup vs baseline: 2.9675x; 2.9675x over previous
#include <cuda_runtime.h>
#include <cstdint>

// PlaceCellNetwork: 50 fixed-point iterations of
//   z_j = C_j + sum_i max(z_i,0) * G[i][j],  Y_j = inv_j * max(z_j, 0)
// Exactly 50 iterations (early exit never fires); rows independent.
// R13 = resubmission of R10 (infra timeouts R7-R12; never executed):
// R5 body (j-packed fma.rn.f32x2, 2 rows/thread, G in smem via LDS.128,
// 4 blocks/SM) with SOFTWARE-PIPELINED relu: the two row streams run half an
// iteration apart -> body = {reluA ; FMA(A,B) sharing G loads ; reluB}.
// reluA is independent of B's FMAs and reluB of A's FMAs, so ALU work always
// has adjacent independent FFMA2s (kills the lockstep ALU phase that capped
// fma at 72.5% in R1/R5). Same ops/regs/LDS as R5; order only.

#define DT    0.05f
#define LBD1  0.005f
#define LBD2  0.005f
#define NITER 50

__device__ __align__(16) float g_G2[104];  // (i*5+p)*2 -> {G[i][2p], G[i][2p+1]} (+pad)
__device__ __align__(16) float g_W2[52];   // (k*5+p)*2 -> {dt*W[2p][k], dt*W[2p+1][k]}
__device__ __align__(16) float g_C0[12];   // C0_j = -dt*b_j - lbd1
__device__ __align__(16) float g_inv[12];  // 1/(lbd2 + M[j][j])

__global__ void setup_kernel(const float* __restrict__ W,
                             const float* __restrict__ M,
                             const float* __restrict__ b) {
    int t = threadIdx.x;
    if (t < 100) {
        int q = t >> 1, half = t & 1;
        int i = q / 5, p = q % 5, j = 2 * p + half;
        float H = (i == j) ? (1.0f - DT) : (-DT * M[i * 10 + j]);
        g_G2[t] = H / (LBD2 + M[i * 10 + i]);
    }
    if (t >= 100 && t < 104) g_G2[t] = 0.0f;
    if (t < 50) {
        int q = t >> 1, half = t & 1;
        int k = q / 5, p = q % 5, j = 2 * p + half;
        g_W2[t] = DT * W[j * 5 + k];
    }
    if (t < 10) {
        g_C0[t]  = -DT * b[t] - LBD1;
        g_inv[t] = 1.0f / (LBD2 + M[t * 10 + t]);
    }
}

typedef unsigned long long u64;

__device__ __forceinline__ u64 f2fma(u64 a, u64 b, u64 c) {
    u64 d;
    asm("fma.rn.f32x2 %0, %1, %2, %3;" : "=l"(d) : "l"(a), "l"(b), "l"(c));
    return d;
}
__device__ __forceinline__ u64 f2pack(float lo, float hi) {
    u64 d;
    asm("mov.b64 %0, {%1, %2};" : "=l"(d) : "f"(lo), "f"(hi));
    return d;
}
__device__ __forceinline__ void f2unpack(u64 v, float& lo, float& hi) {
    asm("mov.b64 {%0, %1}, %2;" : "=f"(lo), "=f"(hi) : "l"(v));
}
// Duplicated relu pair without a MOV: {max(x,+0), max(x,-0)} — the -0 half is
// arithmetically inert as an FMA multiplier. Bit-identical across R3-R5.
__device__ __forceinline__ u64 reludup(float x) {
    return f2pack(fmaxf(x, 0.0f), fmaxf(x, -0.0f));
}

__global__ __launch_bounds__(128, 4)
void pcn_kernel(const float* __restrict__ X, float* __restrict__ Yout,
                int half, int rows) {
    // Folded coupling matrix in shared memory (broadcast reads, conflict-free)
    __shared__ __align__(16) u64 sG[52];
    int t = threadIdx.x;
    if (t < 26) ((ulonglong2*)sG)[t] = ((const ulonglong2*)g_G2)[t];
    __syncthreads();

    int r = blockIdx.x * blockDim.x + t;
    if (r >= half) return;
    int r2 = r + half;
    if (r2 >= rows) r2 = r;   // odd row count guard; benign duplicate

    // Row inputs (coalesced within each stream)
    float xa[5], xb[5];
#pragma unroll
    for (int k = 0; k < 5; k++) xa[k] = X[(size_t)r  * 5 + k];
#pragma unroll
    for (int k = 0; k < 5; k++) xb[k] = X[(size_t)r2 * 5 + k];

    // C = C0 + (x,x)*W2  (k=0 folds the init)
    const u64* C0p = (const u64*)g_C0;
    const u64* W2p = (const u64*)g_W2;
    u64 Ca[5], Cb[5];
    {
        u64 xd0a = f2pack(xa[0], xa[0]);
        u64 xd0b = f2pack(xb[0], xb[0]);
#pragma unroll
        for (int p = 0; p < 5; p++) {
            Ca[p] = f2fma(xd0a, W2p[p], C0p[p]);
            Cb[p] = f2fma(xd0b, W2p[p], C0p[p]);
        }
#pragma unroll
        for (int k = 1; k < 5; k++) {
            u64 xda = f2pack(xa[k], xa[k]);
            u64 xdb = f2pack(xb[k], xb[k]);
#pragma unroll
            for (int p = 0; p < 5; p++) {
                Ca[p] = f2fma(xda, W2p[k * 5 + p], Ca[p]);
                Cb[p] = f2fma(xdb, W2p[k * 5 + p], Cb[p]);
            }
        }
    }

    // z^(1) = C for both rows
    u64 za[5], zb[5];
#pragma unroll
    for (int p = 0; p < 5; p++) { za[p] = Ca[p]; zb[p] = Cb[p]; }

    // Pipeline prologue: row B's V for the first body's FMA block
    u64 Vb[10];
#pragma unroll
    for (int p = 0; p < 5; p++) {
        float lo, hi;
        f2unpack(zb[p], lo, hi);
        Vb[2 * p]     = reludup(lo);
        Vb[2 * p + 1] = reludup(hi);
    }

    const ulonglong2* sG2 = (const ulonglong2*)sG;

    // 49 pipelined bodies. Each body advances BOTH rows by one update:
    //   reluA (indep of B-FMAs) ; FMA block A+B sharing G loads ; reluB (indep of A-FMAs)
    // Per-row op sequence (relu then i-ascending FMA) identical to R1/R5 -> same numerics.
#pragma unroll 1
    for (int it = 0; it < NITER - 1; it++) {
        // Step 1: Va = reludup(za)   [za from previous body's A-FMAs]
        u64 Va[10];
#pragma unroll
        for (int p = 0; p < 5; p++) {
            float lo, hi;
            f2unpack(za[p], lo, hi);
            Va[2 * p]     = reludup(lo);
            Va[2 * p + 1] = reludup(hi);
        }
        // Step 2: FMA block, both rows, one LDS.128 feeds 4 FFMA2 (C folded into i=0)
#pragma unroll
        for (int q = 0; q < 25; q++) {
            ulonglong2 g = sG2[q];
            {
                const int f = 2 * q, i = f / 5, p = f % 5;
                if (i == 0) {
                    za[p] = f2fma(Va[0], g.x, Ca[p]);
                    zb[p] = f2fma(Vb[0], g.x, Cb[p]);
                } else {
                    za[p] = f2fma(Va[i], g.x, za[p]);
                    zb[p] = f2fma(Vb[i], g.x, zb[p]);
                }
            }
            {
                const int f = 2 * q + 1, i = f / 5, p = f % 5;
                if (i == 0) {
                    za[p] = f2fma(Va[0], g.y, Ca[p]);
                    zb[p] = f2fma(Vb[0], g.y, Cb[p]);
                } else {
                    za[p] = f2fma(Va[i], g.y, za[p]);
                    zb[p] = f2fma(Vb[i], g.y, zb[p]);
                }
            }
        }
        // Step 3: Vb = reludup(zb) for the NEXT body's B-FMAs
#pragma unroll
        for (int p = 0; p < 5; p++) {
            float lo, hi;
            f2unpack(zb[p], lo, hi);
            Vb[2 * p]     = reludup(lo);
            Vb[2 * p + 1] = reludup(hi);
        }
    }

    // Final activation + per-output scale; 8-byte vector stores
    float2* out = (float2*)Yout;
#pragma unroll
    for (int p = 0; p < 5; p++) {
        float lo, hi;
        f2unpack(za[p], lo, hi);
        float2 y;
        y.x = fmaxf(lo, 0.0f) * g_inv[2 * p];
        y.y = fmaxf(hi, 0.0f) * g_inv[2 * p + 1];
        out[(size_t)r * 5 + p] = y;
        f2unpack(zb[p], lo, hi);
        y.x = fmaxf(lo, 0.0f) * g_inv[2 * p];
        y.y = fmaxf(hi, 0.0f) * g_inv[2 * p + 1];
        out[(size_t)r2 * 5 + p] = y;
    }
}

extern "C" void kernel_launch(void* const* d_in, const int* in_sizes, int n_in,
                              void* d_out, int out_size) {
    // Identify inputs by element count: X=B*5, W=50, M=100, b=10
    const float *X = nullptr, *W = nullptr, *M = nullptr, *b = nullptr;
    int rows = 0;
    for (int i = 0; i < n_in; i++) {
        int s = in_sizes[i];
        const float* p = (const float*)d_in[i];
        if (s == 100) M = p;
        else if (s == 50) W = p;
        else if (s == 10) b = p;
        else { X = p; rows = s / 5; }
    }

    setup_kernel<<<1, 128>>>(W, M, b);

    int half = (rows + 1) / 2;
    const int threads = 128;
    int blocks = (half + threads - 1) / threads;
    pcn_kernel<<<blocks, threads>>>(X, (float*)d_out, half, rows);
}